// round 14
// baseline (speedup 1.0000x reference)
#include <cuda_runtime.h>
#include <cuda_fp16.h>
#include <cstdint>
#include <math.h>

#define BB 4
#define SS 2048
#define DD 2048
#define XR (BB * SS)
typedef __half h16;

// ---------------- scratch ----------------
__device__ h16  g_x16[(size_t)XR*DD];
__device__ h16  g_w16[3][(size_t)DD*DD];         // fp16 W, natural [K,N]
__device__ h16  g_QKV[3][(size_t)XR*DD];
__device__ float g_P[(size_t)BB*SS*SS];
__device__ h16  g_Ph[(size_t)BB*SS*SS];

// ---------------- helpers ----------------
__device__ __forceinline__ uint32_t smem_u32(const void* p) {
    uint32_t a;
    asm("{ .reg .u64 t; cvta.to.shared.u64 t, %1; cvt.u32.u64 %0, t; }" : "=r"(a) : "l"(p));
    return a;
}
__device__ __forceinline__ void cp16(uint32_t dst, const void* src) {
    asm volatile("cp.async.cg.shared.global [%0], [%1], 16;" :: "r"(dst), "l"(src));
}
__device__ __forceinline__ void ldm4(uint32_t* r, uint32_t addr) {
    asm volatile("ldmatrix.sync.aligned.m8n8.x4.shared.b16 {%0,%1,%2,%3}, [%4];"
                 : "=r"(r[0]), "=r"(r[1]), "=r"(r[2]), "=r"(r[3]) : "r"(addr));
}
__device__ __forceinline__ void ldm4t(uint32_t* r, uint32_t addr) {
    asm volatile("ldmatrix.sync.aligned.m8n8.x4.trans.shared.b16 {%0,%1,%2,%3}, [%4];"
                 : "=r"(r[0]), "=r"(r[1]), "=r"(r[2]), "=r"(r[3]) : "r"(addr));
}
__device__ __forceinline__ void mma_f16(float c[4], const uint32_t a[4],
                                        uint32_t b0, uint32_t b1) {
    asm volatile(
        "mma.sync.aligned.m16n8k16.row.col.f32.f16.f16.f32 "
        "{%0,%1,%2,%3}, {%4,%5,%6,%7}, {%8,%9}, {%0,%1,%2,%3};"
        : "+f"(c[0]), "+f"(c[1]), "+f"(c[2]), "+f"(c[3])
        : "r"(a[0]), "r"(a[1]), "r"(a[2]), "r"(a[3]), "r"(b0), "r"(b1));
}
__device__ __forceinline__ uint32_t pack2(h16 a, h16 b) {
    return (uint32_t)__half_as_ushort(a) | ((uint32_t)__half_as_ushort(b) << 16);
}
__device__ __forceinline__ void gdc_wait() {
    asm volatile("griddepcontrol.wait;" ::: "memory");
}
__device__ __forceinline__ void gdc_launch() {
    asm volatile("griddepcontrol.launch_dependents;" ::: "memory");
}

// ---- GEMM geometry: CTA 128x128, 4 warps of 64x64, BK=64, 3 stages, 2 CTAs/SM ----
#define RST 144                       // A row: 128B data + 16B pad
#define RSTB 272                      // trans-B row: 256B data + 16B pad
#define A_B (128 * RST)               // 18432
#define OB_OFF A_B
#define STG_NT (2 * A_B)              // 36864
#define STG_TR (A_B + 64 * RSTB)      // 35840
#define NST 3
#define SMEM_G (NST * STG_NT)         // 110592 -> 2 CTAs/SM

// C[z+ZOFF] = alpha * A[z+ZOFF] @ op(B[z+ZOFF]);  A: [M,K] rows fp16.
// BTRANS=0: B is [N,K] rows. BTRANS=1: B is [K,N] rows (trans-ldmatrix).
// EPI 0: fp32 to Cf.  EPI 1: fp16 to Ch.
// MODE 0: dense. MODE 1: causal skip (n0 > m0). MODE 2: K truncated at m0+128.
template<int EPI, int MODE, int BTRANS, int ZOFF>
__global__ void __launch_bounds__(128, 2)
gemm_f16(const h16* __restrict__ A, const h16* __restrict__ B,
         float* __restrict__ Cf, h16* __restrict__ Ch,
         int M, int N, int K, size_t sA, size_t sB, size_t sC, float alpha)
{
    constexpr int STG_B = BTRANS ? STG_TR : STG_NT;
    int by = blockIdx.y;
    if (MODE == 1 || MODE == 2) by = gridDim.y - 1 - by;
    const int m0 = by * 128;
    const int n0 = blockIdx.x * 128;
    const int z  = blockIdx.z + ZOFF;
    if (MODE == 1 && n0 > m0) { gdc_launch(); return; }
    int KT = K / 64;
    if (MODE == 2) { int kmax = m0 + 128; if (kmax < K) KT = kmax / 64; }

    extern __shared__ char smem[];
    const uint32_t sbase = smem_u32(smem);
    const int tid  = threadIdx.x;
    const int lane = tid & 31;
    const int wid  = tid >> 5;         // 0..3
    const int wm   = (wid >> 1) * 64;  // 0/64
    const int wn   = (wid & 1) * 64;   // 0/64

    const h16* pA = A + (size_t)z * sA;
    const h16* pB = B + (size_t)z * sB;

    auto load_stage = [&](int s, int kt) {
        if (kt < KT) {
            const uint32_t st = sbase + (uint32_t)s * STG_B;
            const size_t k0 = (size_t)kt * 64;
#pragma unroll
            for (int i = 0; i < 8; i++) {          // A: 128 rows x 8 segs, 128 thr
                const int slot = tid + i * 128;
                const int row = slot >> 3;
                const int seg = slot & 7;
                cp16(st + (uint32_t)(row * RST + seg * 16),
                     pA + (size_t)(m0 + row) * K + k0 + seg * 8);
            }
            if (BTRANS) {
#pragma unroll
                for (int i = 0; i < 8; i++) {      // B: 64 k-rows x 16 segs
                    const int slot = tid + i * 128;
                    const int row = slot >> 4;
                    const int seg = slot & 15;
                    cp16(st + OB_OFF + (uint32_t)(row * RSTB + seg * 16),
                         pB + (k0 + row) * (size_t)N + n0 + seg * 8);
                }
            } else {
#pragma unroll
                for (int i = 0; i < 8; i++) {      // B: 128 n-rows x 8 segs
                    const int slot = tid + i * 128;
                    const int row = slot >> 3;
                    const int seg = slot & 7;
                    cp16(st + OB_OFF + (uint32_t)(row * RST + seg * 16),
                         pB + (size_t)(n0 + row) * K + k0 + seg * 8);
                }
            }
        }
        asm volatile("cp.async.commit_group;" ::: "memory");
    };

    // ldmatrix lane addressing
    const int arow = lane & 15;
    const int akh  = lane >> 4;
    const uint32_t aoff = (uint32_t)((wm + arow) * RST + akh * 16);
    const int nrow = (lane & 7) + ((lane >> 4) << 3);
    const int bkh  = (lane >> 3) & 1;
    const uint32_t boffN = (uint32_t)((wn + nrow) * RST + bkh * 16);
    const int btrow = (lane & 7) + (((lane >> 3) & 1) << 3);
    const uint32_t boffT = (uint32_t)(btrow * RSTB + (((lane >> 4) << 3) + wn) * 2);

    float acc[4][8][4];
#pragma unroll
    for (int i = 0; i < 4; i++)
#pragma unroll
        for (int j = 0; j < 8; j++)
#pragma unroll
            for (int q = 0; q < 4; q++) acc[i][j][q] = 0.0f;

    gdc_wait();
    load_stage(0, 0);
    load_stage(1, 1);

    uint32_t af[2][16], bf[2][16];
    auto load_frags = [&](int buf, int ks, uint32_t stg) {
#pragma unroll
        for (int mt = 0; mt < 4; mt++)
            ldm4(&af[buf][mt * 4], stg + aoff + mt * (16 * RST) + ks * 32);
#pragma unroll
        for (int ntp = 0; ntp < 4; ntp++) {
            if (BTRANS)
                ldm4t(&bf[buf][ntp * 4], stg + OB_OFF + boffT + ks * (16 * RSTB) + ntp * 32);
            else
                ldm4(&bf[buf][ntp * 4], stg + OB_OFF + boffN + ntp * (16 * RST) + ks * 32);
        }
    };

    for (int it = 0; it < KT; it++) {
        const int s = it % NST;
        asm volatile("cp.async.wait_group 1;" ::: "memory");
        __syncthreads();
        load_stage((it + 2) % NST, it + 2);   // stage (it-1)%NST: readers done last iter
        const uint32_t stg = sbase + (uint32_t)s * STG_B;
        load_frags(0, 0, stg);
#pragma unroll
        for (int ks = 0; ks < 4; ks++) {
            const int cb = ks & 1;
            if (ks < 3) load_frags(cb ^ 1, ks + 1, stg);   // prefetch next frags
#pragma unroll
            for (int mt = 0; mt < 4; mt++)
#pragma unroll
                for (int nt = 0; nt < 8; nt++) {
                    const int bi = (nt >> 1) * 4 + (nt & 1) * 2;
                    mma_f16(acc[mt][nt], &af[cb][mt * 4], bf[cb][bi], bf[cb][bi + 1]);
                }
        }
    }

    gdc_launch();

    // ---- epilogue ----
    const int r0 = wm + (lane >> 2);
    const int c0 = wn + (lane & 3) * 2;
#pragma unroll
    for (int mt = 0; mt < 4; mt++) {
#pragma unroll
        for (int nt = 0; nt < 8; nt++) {
            const int row = m0 + r0 + mt * 16;
            const int col = n0 + c0 + nt * 8;
            const float v0 = acc[mt][nt][0] * alpha, v1 = acc[mt][nt][1] * alpha;
            const float v2 = acc[mt][nt][2] * alpha, v3 = acc[mt][nt][3] * alpha;
            const size_t o0 = (size_t)z * sC + (size_t)row * N + col;
            const size_t o1 = (size_t)z * sC + (size_t)(row + 8) * N + col;
            if (EPI == 0) {
                Cf[o0] = v0; Cf[o0 + 1] = v1;
                Cf[o1] = v2; Cf[o1 + 1] = v3;
            } else {
                *reinterpret_cast<uint32_t*>(Ch + o0) =
                    pack2(__float2half_rn(v0), __float2half_rn(v1));
                *reinterpret_cast<uint32_t*>(Ch + o1) =
                    pack2(__float2half_rn(v2), __float2half_rn(v3));
            }
        }
    }
}

// ---------------- conversion (x + 3 W fused) / softmax ----------------
__global__ __launch_bounds__(256) void convert_all_kernel(
    const float* __restrict__ x, const float* __restrict__ W0,
    const float* __restrict__ W1, const float* __restrict__ W2,
    h16* __restrict__ x16, h16* __restrict__ w16)
{
    const int zz = blockIdx.z;
    const float* in;
    h16* out;
    size_t n4;
    if (zz == 0) { in = x;  out = x16;                          n4 = (size_t)XR * DD / 4; }
    else {
        in  = (zz == 1) ? W0 : (zz == 2) ? W1 : W2;
        out = w16 + (size_t)(zz - 1) * DD * DD;
        n4  = (size_t)DD * DD / 4;
    }
    for (size_t i = (size_t)blockIdx.x * 256 + threadIdx.x; i < n4; i += (size_t)gridDim.x * 256) {
        const float4 v = reinterpret_cast<const float4*>(in)[i];
        uint2 o;
        o.x = pack2(__float2half_rn(v.x), __float2half_rn(v.y));
        o.y = pack2(__float2half_rn(v.z), __float2half_rn(v.w));
        reinterpret_cast<uint2*>(out)[i] = o;
    }
    gdc_launch();
}

// causal softmax, warp-shuffle reductions, float4 I/O. One block per row.
__global__ __launch_bounds__(256) void softmax_kernel(
    const float* __restrict__ P, h16* __restrict__ Ph)
{
    const int row = blockIdx.x & (SS - 1);
    const int b   = blockIdx.x >> 11;
    const size_t base = ((size_t)b * SS + row) * SS;
    const int L = row + 1;
    const int tid  = threadIdx.x;
    const int lane = tid & 31;
    const int wrp  = tid >> 5;

    gdc_wait();
    const float4* P4 = reinterpret_cast<const float4*>(P + base);
    float4 va = P4[tid];
    float4 vb = P4[tid + 256];
    const int e0 = tid * 4;
    const int e1 = 1024 + tid * 4;

    float v[8] = {va.x, va.y, va.z, va.w, vb.x, vb.y, vb.z, vb.w};
    float m = -INFINITY;
#pragma unroll
    for (int q = 0; q < 4; q++) if (e0 + q < L) m = fmaxf(m, v[q]);
#pragma unroll
    for (int q = 0; q < 4; q++) if (e1 + q < L) m = fmaxf(m, v[4 + q]);

    __shared__ float red[8];
#pragma unroll
    for (int o = 16; o > 0; o >>= 1) m = fmaxf(m, __shfl_xor_sync(0xFFFFFFFFu, m, o));
    if (lane == 0) red[wrp] = m;
    __syncthreads();
#pragma unroll
    for (int w = 0; w < 8; w++) m = fmaxf(m, red[w]);
    __syncthreads();

    float sum = 0.0f;
#pragma unroll
    for (int q = 0; q < 4; q++) {
        v[q]     = (e0 + q < L) ? __expf(v[q] - m)     : 0.0f;
        v[4 + q] = (e1 + q < L) ? __expf(v[4 + q] - m) : 0.0f;
        sum += v[q] + v[4 + q];
    }
#pragma unroll
    for (int o = 16; o > 0; o >>= 1) sum += __shfl_xor_sync(0xFFFFFFFFu, sum, o);
    if (lane == 0) red[wrp] = sum;
    __syncthreads();
    sum = 0.0f;
#pragma unroll
    for (int w = 0; w < 8; w++) sum += red[w];
    const float inv = 1.0f / sum;
    gdc_launch();

    uint2* O4 = reinterpret_cast<uint2*>(Ph + base);
    uint2 oa, ob;
    oa.x = pack2(__float2half_rn(v[0] * inv), __float2half_rn(v[1] * inv));
    oa.y = pack2(__float2half_rn(v[2] * inv), __float2half_rn(v[3] * inv));
    ob.x = pack2(__float2half_rn(v[4] * inv), __float2half_rn(v[5] * inv));
    ob.y = pack2(__float2half_rn(v[6] * inv), __float2half_rn(v[7] * inv));
    O4[tid] = oa;
    O4[tid + 256] = ob;
}

// ---------------- PDL launch helper ----------------
static void launch_pdl(const void* func, dim3 grid, dim3 block, size_t smem,
                       void** args, cudaStream_t st)
{
    cudaLaunchConfig_t cfg = {};
    cfg.gridDim = grid;
    cfg.blockDim = block;
    cfg.dynamicSmemBytes = smem;
    cfg.stream = st;
    cudaLaunchAttribute attr[1];
    attr[0].id = cudaLaunchAttributeProgrammaticStreamSerialization;
    attr[0].val.programmaticStreamSerializationAllowed = 1;
    cfg.attrs = attr;
    cfg.numAttrs = 1;
    if (cudaLaunchKernelExC(&cfg, func, args) != cudaSuccess) {
        cudaLaunchKernel(func, grid, block, args, smem, st);
    }
}

// ---------------- launch ----------------
extern "C" void kernel_launch(void* const* d_in, const int* in_sizes, int n_in,
                              void* d_out, int out_size)
{
    const float* x  = (const float*)d_in[0];
    const float* Wq = (const float*)d_in[1];
    const float* Wk = (const float*)d_in[2];
    const float* Wv = (const float*)d_in[3];
    float* out = (float*)d_out;

    h16 *x16, *w16, *QKV, *Ph;
    float* P;
    cudaGetSymbolAddress((void**)&x16, g_x16);
    cudaGetSymbolAddress((void**)&w16, g_w16);
    cudaGetSymbolAddress((void**)&QKV, g_QKV);
    cudaGetSymbolAddress((void**)&P,   g_P);
    cudaGetSymbolAddress((void**)&Ph,  g_Ph);

    cudaFuncSetAttribute(gemm_f16<1,0,1,0>, cudaFuncAttributeMaxDynamicSharedMemorySize, SMEM_G);
    cudaFuncSetAttribute(gemm_f16<1,0,1,2>, cudaFuncAttributeMaxDynamicSharedMemorySize, SMEM_G);
    cudaFuncSetAttribute(gemm_f16<0,1,0,0>, cudaFuncAttributeMaxDynamicSharedMemorySize, SMEM_G);
    cudaFuncSetAttribute(gemm_f16<0,2,1,0>, cudaFuncAttributeMaxDynamicSharedMemorySize, SMEM_G);

    // one-time side stream + events (reused every call; no device-mem allocs)
    static cudaStream_t s2 = nullptr;
    static cudaEvent_t evFork = nullptr, evJoin = nullptr;
    if (s2 == nullptr) {
        cudaStreamCreateWithFlags(&s2, cudaStreamNonBlocking);
        cudaEventCreateWithFlags(&evFork, cudaEventDisableTiming);
        cudaEventCreateWithFlags(&evJoin, cudaEventDisableTiming);
    }

    size_t WSZ = (size_t)DD * DD;
    size_t QSZ = (size_t)XR * DD;
    const float scale = 1.0f / sqrtf((float)DD);
    h16* nullh = nullptr;
    float* nullf = nullptr;

    // 1. fp32 -> fp16 conversions (x and all W) on stream 0
    convert_all_kernel<<<dim3(2048, 1, 4), 256>>>(x, Wq, Wk, Wv, x16, w16);

    // fork: s2 waits on conversions
    cudaEventRecord(evFork, 0);
    cudaStreamWaitEvent(s2, evFork, 0);

    // 2a. V projection (z=2) on side stream — needed only by PV
    {
        int M = XR, N = DD, K = DD;
        size_t sA = 0, sB = WSZ, sC = QSZ;
        float alpha = 1.0f;
        void* args[] = {&x16, &w16, &nullf, &QKV, &M, &N, &K, &sA, &sB, &sC, &alpha};
        launch_pdl((const void*)gemm_f16<1,0,1,2>, dim3(DD/128, XR/128, 1), 128, SMEM_G, args, s2);
    }

    // 2b. Q,K projections (z=0,1) on stream 0
    {
        int M = XR, N = DD, K = DD;
        size_t sA = 0, sB = WSZ, sC = QSZ;
        float alpha = 1.0f;
        void* args[] = {&x16, &w16, &nullf, &QKV, &M, &N, &K, &sA, &sB, &sC, &alpha};
        launch_pdl((const void*)gemm_f16<1,0,1,0>, dim3(DD/128, XR/128, 2), 128, SMEM_G, args, 0);
    }

    // 3. scores: P[b] = scale * Q[b] @ K[b]^T (causal skip) on stream 0
    {
        int M = SS, N = SS, K = DD;
        size_t sA = (size_t)SS*DD, sB = (size_t)SS*DD, sC = (size_t)SS*SS;
        float alpha = scale;
        const h16* Qp = QKV;
        const h16* Kp = QKV + QSZ;
        void* args[] = {&Qp, &Kp, &P, &nullh, &M, &N, &K, &sA, &sB, &sC, &alpha};
        launch_pdl((const void*)gemm_f16<0,1,0,0>, dim3(SS/128, SS/128, BB), 128, SMEM_G, args, 0);
    }

    // 4. causal softmax -> fp16 P on stream 0
    {
        const float* Pp = P;
        void* args[] = {&Pp, &Ph};
        launch_pdl((const void*)softmax_kernel, dim3(BB * SS), 256, 0, args, 0);
    }

    // join: stream 0 waits for V projection
    cudaEventRecord(evJoin, s2);
    cudaStreamWaitEvent(0, evJoin, 0);

    // 5. out[b] = P[b] @ V[b] (K truncated at diagonal) on stream 0
    {
        int M = SS, N = DD, K = SS;
        size_t sA = (size_t)SS*SS, sB = (size_t)SS*DD, sC = (size_t)SS*DD;
        float alpha = 1.0f;
        const h16* Pp = Ph;
        const h16* Vp = QKV + 2*QSZ;
        void* args[] = {&Pp, &Vp, &out, &nullh, &M, &N, &K, &sA, &sB, &sC, &alpha};
        launch_pdl((const void*)gemm_f16<0,2,1,0>, dim3(DD/128, SS/128, BB), 128, SMEM_G, args, 0);
    }
}

// round 15
// speedup vs baseline: 1.0101x; 1.0101x over previous
#include <cuda_runtime.h>
#include <cuda_fp16.h>
#include <cstdint>
#include <math.h>

#define BB 4
#define SS 2048
#define DD 2048
#define XR (BB * SS)
typedef __half h16;

// ---------------- scratch ----------------
__device__ h16  g_x16[(size_t)XR*DD];
__device__ h16  g_w16[3][(size_t)DD*DD];         // fp16 W, natural [K,N]
__device__ h16  g_QKV[3][(size_t)XR*DD];
__device__ float g_P[(size_t)BB*SS*SS];          // reused as fp16 score buffer
__device__ h16  g_Ph[(size_t)BB*SS*SS];

// ---------------- helpers ----------------
__device__ __forceinline__ uint32_t smem_u32(const void* p) {
    uint32_t a;
    asm("{ .reg .u64 t; cvta.to.shared.u64 t, %1; cvt.u32.u64 %0, t; }" : "=r"(a) : "l"(p));
    return a;
}
__device__ __forceinline__ void cp16(uint32_t dst, const void* src) {
    asm volatile("cp.async.cg.shared.global [%0], [%1], 16;" :: "r"(dst), "l"(src));
}
__device__ __forceinline__ void ldm4(uint32_t* r, uint32_t addr) {
    asm volatile("ldmatrix.sync.aligned.m8n8.x4.shared.b16 {%0,%1,%2,%3}, [%4];"
                 : "=r"(r[0]), "=r"(r[1]), "=r"(r[2]), "=r"(r[3]) : "r"(addr));
}
__device__ __forceinline__ void ldm4t(uint32_t* r, uint32_t addr) {
    asm volatile("ldmatrix.sync.aligned.m8n8.x4.trans.shared.b16 {%0,%1,%2,%3}, [%4];"
                 : "=r"(r[0]), "=r"(r[1]), "=r"(r[2]), "=r"(r[3]) : "r"(addr));
}
__device__ __forceinline__ void mma_f16(float c[4], const uint32_t a[4],
                                        uint32_t b0, uint32_t b1) {
    asm volatile(
        "mma.sync.aligned.m16n8k16.row.col.f32.f16.f16.f32 "
        "{%0,%1,%2,%3}, {%4,%5,%6,%7}, {%8,%9}, {%0,%1,%2,%3};"
        : "+f"(c[0]), "+f"(c[1]), "+f"(c[2]), "+f"(c[3])
        : "r"(a[0]), "r"(a[1]), "r"(a[2]), "r"(a[3]), "r"(b0), "r"(b1));
}
__device__ __forceinline__ uint32_t pack2(h16 a, h16 b) {
    return (uint32_t)__half_as_ushort(a) | ((uint32_t)__half_as_ushort(b) << 16);
}
__device__ __forceinline__ void gdc_wait() {
    asm volatile("griddepcontrol.wait;" ::: "memory");
}
__device__ __forceinline__ void gdc_launch() {
    asm volatile("griddepcontrol.launch_dependents;" ::: "memory");
}

// ---------------- GEMM geometry: CTA 128x128, warp 64x32, BK=64, 3 stages ----
#define RST 144                       // A row: 128B data + 16B pad
#define RSTB 272                      // trans-B row: 256B data + 16B pad
#define A_B (128 * RST)               // 18432
#define OB_OFF A_B
#define STG_NT (2 * A_B)              // 36864
#define STG_TR (A_B + 64 * RSTB)      // 35840
#define NST 3
#define SMEM_G (NST * STG_NT)         // 110592 -> 2 CTAs/SM

// C[z+ZOFF] = alpha * A[z+ZOFF] @ op(B[z+ZOFF]);  A: [M,K] rows fp16.
// BTRANS=0: B is [N,K] rows. BTRANS=1: B is [K,N] rows (trans-ldmatrix).
// EPI 0: fp32 to Cf.  EPI 1: fp16 to Ch.
// MODE 0: dense. MODE 2: K truncated at m0+128 (heavy m-tiles first).
// MODE 3: triangular-packed causal grid: blockIdx.x = packed lower-tri tile id
//         (heavy m first), blockIdx.z = batch.
template<int EPI, int MODE, int BTRANS, int ZOFF>
__global__ void __launch_bounds__(256, 2)
gemm_f16(const h16* __restrict__ A, const h16* __restrict__ B,
         float* __restrict__ Cf, h16* __restrict__ Ch,
         int M, int N, int K, size_t sA, size_t sB, size_t sC, float alpha)
{
    constexpr int STG_B = BTRANS ? STG_TR : STG_NT;
    int m0, n0;
    if (MODE == 3) {
        const int t = (int)(gridDim.x - 1 - blockIdx.x);   // heavy (large m) first
        int mt = (int)((sqrtf(8.0f * (float)t + 1.0f) - 1.0f) * 0.5f);
        while ((mt + 1) * (mt + 2) / 2 <= t) mt++;
        while (mt * (mt + 1) / 2 > t) mt--;
        const int nt = t - mt * (mt + 1) / 2;
        m0 = mt * 128;
        n0 = nt * 128;
    } else {
        int by = blockIdx.y;
        if (MODE == 2) by = gridDim.y - 1 - by;
        m0 = by * 128;
        n0 = blockIdx.x * 128;
    }
    const int z = blockIdx.z + ZOFF;
    int KT = K / 64;
    if (MODE == 2) { int kmax = m0 + 128; if (kmax < K) KT = kmax / 64; }

    extern __shared__ char smem[];
    const uint32_t sbase = smem_u32(smem);
    const int tid  = threadIdx.x;
    const int lane = tid & 31;
    const int wid  = tid >> 5;
    const int wm   = (wid >> 2) * 64;
    const int wn   = (wid & 3) * 32;

    const h16* pA = A + (size_t)z * sA;
    const h16* pB = B + (size_t)z * sB;

    auto load_stage = [&](int s, int kt) {
        if (kt < KT) {
            const uint32_t st = sbase + (uint32_t)s * STG_B;
            const size_t k0 = (size_t)kt * 64;
#pragma unroll
            for (int i = 0; i < 4; i++) {          // A: 128 rows x 8 segs
                const int slot = tid + i * 256;
                const int row = slot >> 3;
                const int seg = slot & 7;
                cp16(st + (uint32_t)(row * RST + seg * 16),
                     pA + (size_t)(m0 + row) * K + k0 + seg * 8);
            }
            if (BTRANS) {
#pragma unroll
                for (int i = 0; i < 4; i++) {      // B: 64 k-rows x 16 segs
                    const int slot = tid + i * 256;
                    const int row = slot >> 4;
                    const int seg = slot & 15;
                    cp16(st + OB_OFF + (uint32_t)(row * RSTB + seg * 16),
                         pB + (k0 + row) * (size_t)N + n0 + seg * 8);
                }
            } else {
#pragma unroll
                for (int i = 0; i < 4; i++) {      // B: 128 n-rows x 8 segs
                    const int slot = tid + i * 256;
                    const int row = slot >> 3;
                    const int seg = slot & 7;
                    cp16(st + OB_OFF + (uint32_t)(row * RST + seg * 16),
                         pB + (size_t)(n0 + row) * K + k0 + seg * 8);
                }
            }
        }
        asm volatile("cp.async.commit_group;" ::: "memory");
    };

    // ldmatrix lane addressing
    const int arow = lane & 15;
    const int akh  = lane >> 4;
    const uint32_t aoff = (uint32_t)((wm + arow) * RST + akh * 16);
    const int nrow = (lane & 7) + ((lane >> 4) << 3);
    const int bkh  = (lane >> 3) & 1;
    const uint32_t boffN = (uint32_t)((wn + nrow) * RST + bkh * 16);
    const int btrow = (lane & 7) + (((lane >> 3) & 1) << 3);
    const uint32_t boffT = (uint32_t)(btrow * RSTB + (((lane >> 4) << 3) + wn) * 2);

    float acc[4][4][4];
#pragma unroll
    for (int i = 0; i < 4; i++)
#pragma unroll
        for (int j = 0; j < 4; j++)
#pragma unroll
            for (int q = 0; q < 4; q++) acc[i][j][q] = 0.0f;

    gdc_wait();
    load_stage(0, 0);
    load_stage(1, 1);

    for (int it = 0; it < KT; it++) {
        const int s = it % NST;
        asm volatile("cp.async.wait_group 1;" ::: "memory");
        __syncthreads();
        load_stage((it + 2) % NST, it + 2);   // stage (it-1)%NST: readers done last iter
        const uint32_t stg = sbase + (uint32_t)s * STG_B;
#pragma unroll
        for (int ks = 0; ks < 4; ks++) {
            uint32_t a[4][4], b[4][2];
#pragma unroll
            for (int mt = 0; mt < 4; mt++)
                ldm4(a[mt], stg + aoff + mt * (16 * RST) + ks * 32);
#pragma unroll
            for (int ntp = 0; ntp < 2; ntp++) {
                uint32_t t[4];
                if (BTRANS)
                    ldm4t(t, stg + OB_OFF + boffT + ks * (16 * RSTB) + ntp * 32);
                else
                    ldm4(t, stg + OB_OFF + boffN + ntp * (16 * RST) + ks * 32);
                b[2*ntp][0] = t[0]; b[2*ntp][1] = t[1];
                b[2*ntp+1][0] = t[2]; b[2*ntp+1][1] = t[3];
            }
#pragma unroll
            for (int mt = 0; mt < 4; mt++)
#pragma unroll
                for (int nt = 0; nt < 4; nt++)
                    mma_f16(acc[mt][nt], a[mt], b[nt][0], b[nt][1]);
        }
    }

    gdc_launch();

    // ---- epilogue ----
    const int r0 = wm + (lane >> 2);
    const int c0 = wn + (lane & 3) * 2;
#pragma unroll
    for (int mt = 0; mt < 4; mt++) {
#pragma unroll
        for (int nt = 0; nt < 4; nt++) {
            const int row = m0 + r0 + mt * 16;
            const int col = n0 + c0 + nt * 8;
            const float v0 = acc[mt][nt][0] * alpha, v1 = acc[mt][nt][1] * alpha;
            const float v2 = acc[mt][nt][2] * alpha, v3 = acc[mt][nt][3] * alpha;
            const size_t o0 = (size_t)z * sC + (size_t)row * N + col;
            const size_t o1 = (size_t)z * sC + (size_t)(row + 8) * N + col;
            if (EPI == 0) {
                Cf[o0] = v0; Cf[o0 + 1] = v1;
                Cf[o1] = v2; Cf[o1 + 1] = v3;
            } else {
                *reinterpret_cast<uint32_t*>(Ch + o0) =
                    pack2(__float2half_rn(v0), __float2half_rn(v1));
                *reinterpret_cast<uint32_t*>(Ch + o1) =
                    pack2(__float2half_rn(v2), __float2half_rn(v3));
            }
        }
    }
}

// ---------------- conversion (x + 3 W fused) / softmax ----------------
__global__ __launch_bounds__(256) void convert_all_kernel(
    const float* __restrict__ x, const float* __restrict__ W0,
    const float* __restrict__ W1, const float* __restrict__ W2,
    h16* __restrict__ x16, h16* __restrict__ w16)
{
    const int zz = blockIdx.z;
    const float* in;
    h16* out;
    size_t n4;
    if (zz == 0) { in = x;  out = x16;                          n4 = (size_t)XR * DD / 4; }
    else {
        in  = (zz == 1) ? W0 : (zz == 2) ? W1 : W2;
        out = w16 + (size_t)(zz - 1) * DD * DD;
        n4  = (size_t)DD * DD / 4;
    }
    for (size_t i = (size_t)blockIdx.x * 256 + threadIdx.x; i < n4; i += (size_t)gridDim.x * 256) {
        const float4 v = reinterpret_cast<const float4*>(in)[i];
        uint2 o;
        o.x = pack2(__float2half_rn(v.x), __float2half_rn(v.y));
        o.y = pack2(__float2half_rn(v.z), __float2half_rn(v.w));
        reinterpret_cast<uint2*>(out)[i] = o;
    }
    gdc_launch();
}

// causal softmax over fp16 scores (scaled in GEMM); one block of 256 per row.
// Each thread handles 8 contiguous h16 (one uint4) of the 2048-wide row.
__global__ __launch_bounds__(256) void softmax_kernel(
    const h16* __restrict__ S, h16* __restrict__ Ph)
{
    const int row = blockIdx.x & (SS - 1);
    const int b   = blockIdx.x >> 11;
    const size_t base = ((size_t)b * SS + row) * SS;
    const int L = row + 1;
    const int tid  = threadIdx.x;
    const int lane = tid & 31;
    const int wrp  = tid >> 5;

    gdc_wait();
    const uint4 sv = reinterpret_cast<const uint4*>(S + base)[tid];
    const int e0 = tid * 8;
    float v[8];
    {
        float2 f;
        f = __half22float2(*reinterpret_cast<const __half2*>(&sv.x)); v[0] = f.x; v[1] = f.y;
        f = __half22float2(*reinterpret_cast<const __half2*>(&sv.y)); v[2] = f.x; v[3] = f.y;
        f = __half22float2(*reinterpret_cast<const __half2*>(&sv.z)); v[4] = f.x; v[5] = f.y;
        f = __half22float2(*reinterpret_cast<const __half2*>(&sv.w)); v[6] = f.x; v[7] = f.y;
    }

    float m = -INFINITY;
#pragma unroll
    for (int q = 0; q < 8; q++) if (e0 + q < L) m = fmaxf(m, v[q]);

    __shared__ float red[8];
#pragma unroll
    for (int o = 16; o > 0; o >>= 1) m = fmaxf(m, __shfl_xor_sync(0xFFFFFFFFu, m, o));
    if (lane == 0) red[wrp] = m;
    __syncthreads();
#pragma unroll
    for (int w = 0; w < 8; w++) m = fmaxf(m, red[w]);
    __syncthreads();

    float sum = 0.0f;
#pragma unroll
    for (int q = 0; q < 8; q++) {
        v[q] = (e0 + q < L) ? __expf(v[q] - m) : 0.0f;
        sum += v[q];
    }
#pragma unroll
    for (int o = 16; o > 0; o >>= 1) sum += __shfl_xor_sync(0xFFFFFFFFu, sum, o);
    if (lane == 0) red[wrp] = sum;
    __syncthreads();
    sum = 0.0f;
#pragma unroll
    for (int w = 0; w < 8; w++) sum += red[w];
    const float inv = 1.0f / sum;
    gdc_launch();

    uint4 ov;
    ov.x = pack2(__float2half_rn(v[0] * inv), __float2half_rn(v[1] * inv));
    ov.y = pack2(__float2half_rn(v[2] * inv), __float2half_rn(v[3] * inv));
    ov.z = pack2(__float2half_rn(v[4] * inv), __float2half_rn(v[5] * inv));
    ov.w = pack2(__float2half_rn(v[6] * inv), __float2half_rn(v[7] * inv));
    reinterpret_cast<uint4*>(Ph + base)[tid] = ov;
}

// zero the strictly-upper-triangular score region? Not needed: softmax masks by L,
// and PV reads Ph (fully written by softmax). (kept as comment for clarity)

// ---------------- PDL launch helper ----------------
static void launch_pdl(const void* func, dim3 grid, dim3 block, size_t smem,
                       void** args, cudaStream_t st)
{
    cudaLaunchConfig_t cfg = {};
    cfg.gridDim = grid;
    cfg.blockDim = block;
    cfg.dynamicSmemBytes = smem;
    cfg.stream = st;
    cudaLaunchAttribute attr[1];
    attr[0].id = cudaLaunchAttributeProgrammaticStreamSerialization;
    attr[0].val.programmaticStreamSerializationAllowed = 1;
    cfg.attrs = attr;
    cfg.numAttrs = 1;
    if (cudaLaunchKernelExC(&cfg, func, args) != cudaSuccess) {
        cudaLaunchKernel(func, grid, block, args, smem, st);
    }
}

// ---------------- launch ----------------
extern "C" void kernel_launch(void* const* d_in, const int* in_sizes, int n_in,
                              void* d_out, int out_size)
{
    const float* x  = (const float*)d_in[0];
    const float* Wq = (const float*)d_in[1];
    const float* Wk = (const float*)d_in[2];
    const float* Wv = (const float*)d_in[3];
    float* out = (float*)d_out;

    h16 *x16, *w16, *QKV, *Ph;
    float* P;
    cudaGetSymbolAddress((void**)&x16, g_x16);
    cudaGetSymbolAddress((void**)&w16, g_w16);
    cudaGetSymbolAddress((void**)&QKV, g_QKV);
    cudaGetSymbolAddress((void**)&P,   g_P);
    cudaGetSymbolAddress((void**)&Ph,  g_Ph);
    h16* Sh = (h16*)P;   // fp16 score buffer aliasing g_P

    cudaFuncSetAttribute(gemm_f16<1,0,1,0>, cudaFuncAttributeMaxDynamicSharedMemorySize, SMEM_G);
    cudaFuncSetAttribute(gemm_f16<1,0,1,2>, cudaFuncAttributeMaxDynamicSharedMemorySize, SMEM_G);
    cudaFuncSetAttribute(gemm_f16<1,3,0,0>, cudaFuncAttributeMaxDynamicSharedMemorySize, SMEM_G);
    cudaFuncSetAttribute(gemm_f16<0,2,1,0>, cudaFuncAttributeMaxDynamicSharedMemorySize, SMEM_G);

    // one-time side stream + events (reused every call; no device-mem allocs)
    static cudaStream_t s2 = nullptr;
    static cudaEvent_t evFork = nullptr, evJoin = nullptr;
    if (s2 == nullptr) {
        cudaStreamCreateWithFlags(&s2, cudaStreamNonBlocking);
        cudaEventCreateWithFlags(&evFork, cudaEventDisableTiming);
        cudaEventCreateWithFlags(&evJoin, cudaEventDisableTiming);
    }

    size_t WSZ = (size_t)DD * DD;
    size_t QSZ = (size_t)XR * DD;
    const float scale = 1.0f / sqrtf((float)DD);
    h16* nullh = nullptr;
    float* nullf = nullptr;

    // 1. fp32 -> fp16 conversions (x and all W) on stream 0
    convert_all_kernel<<<dim3(2048, 1, 4), 256>>>(x, Wq, Wk, Wv, x16, w16);

    // fork: s2 waits on conversions
    cudaEventRecord(evFork, 0);
    cudaStreamWaitEvent(s2, evFork, 0);

    // 2a. V projection (z=2) on side stream — needed only by PV
    {
        int M = XR, N = DD, K = DD;
        size_t sA = 0, sB = WSZ, sC = QSZ;
        float alpha = 1.0f;
        void* args[] = {&x16, &w16, &nullf, &QKV, &M, &N, &K, &sA, &sB, &sC, &alpha};
        launch_pdl((const void*)gemm_f16<1,0,1,2>, dim3(DD/128, XR/128, 1), 256, SMEM_G, args, s2);
    }

    // 2b. Q,K projections (z=0,1) on stream 0
    {
        int M = XR, N = DD, K = DD;
        size_t sA = 0, sB = WSZ, sC = QSZ;
        float alpha = 1.0f;
        void* args[] = {&x16, &w16, &nullf, &QKV, &M, &N, &K, &sA, &sB, &sC, &alpha};
        launch_pdl((const void*)gemm_f16<1,0,1,0>, dim3(DD/128, XR/128, 2), 256, SMEM_G, args, 0);
    }

    // 3. scores (fp16 out, scaled): S[b] = scale * Q[b] @ K[b]^T
    //    triangular-packed grid: 136 live tiles per batch, heavy-m first
    {
        int M = SS, N = SS, K = DD;
        size_t sA = (size_t)SS*DD, sB = (size_t)SS*DD, sC = (size_t)SS*SS;
        float alpha = scale;
        const h16* Qp = QKV;
        const h16* Kp = QKV + QSZ;
        void* args[] = {&Qp, &Kp, &nullf, &Sh, &M, &N, &K, &sA, &sB, &sC, &alpha};
        launch_pdl((const void*)gemm_f16<1,3,0,0>, dim3(136, 1, BB), 256, SMEM_G, args, 0);
    }

    // 4. causal softmax (fp16 in) -> fp16 P on stream 0
    {
        const h16* Sp = Sh;
        void* args[] = {&Sp, &Ph};
        launch_pdl((const void*)softmax_kernel, dim3(BB * SS), 256, 0, args, 0);
    }

    // join: stream 0 waits for V projection
    cudaEventRecord(evJoin, s2);
    cudaStreamWaitEvent(0, evJoin, 0);

    // 5. out[b] = P[b] @ V[b] (K truncated at diagonal) on stream 0
    {
        int M = SS, N = DD, K = SS;
        size_t sA = (size_t)SS*SS, sB = (size_t)SS*DD, sC = (size_t)SS*DD;
        float alpha = 1.0f;
        const h16* Pp = Ph;
        const h16* Vp = QKV + 2*QSZ;
        void* args[] = {&Pp, &Vp, &out, &nullh, &M, &N, &K, &sA, &sB, &sC, &alpha};
        launch_pdl((const void*)gemm_f16<0,2,1,0>, dim3(DD/128, SS/128, BB), 256, SMEM_G, args, 0);
    }
}

// round 17
// speedup vs baseline: 1.0187x; 1.0085x over previous
#include <cuda_runtime.h>
#include <cuda_fp16.h>
#include <cstdint>
#include <math.h>

#define BB 4
#define SS 2048
#define DD 2048
#define XR (BB * SS)
typedef __half h16;

// ---------------- scratch ----------------
__device__ h16  g_x16[(size_t)XR*DD];
__device__ h16  g_w16[3][(size_t)DD*DD];         // fp16 W, natural [K,N]
__device__ h16  g_QKV[3][(size_t)XR*DD];
__device__ float g_P[(size_t)BB*SS*SS];          // aliased as fp16 score buffer
__device__ h16  g_Ph[(size_t)BB*SS*SS];

// ---------------- helpers ----------------
__device__ __forceinline__ uint32_t smem_u32(const void* p) {
    uint32_t a;
    asm("{ .reg .u64 t; cvta.to.shared.u64 t, %1; cvt.u32.u64 %0, t; }" : "=r"(a) : "l"(p));
    return a;
}
__device__ __forceinline__ void cp16(uint32_t dst, const void* src) {
    asm volatile("cp.async.cg.shared.global [%0], [%1], 16;" :: "r"(dst), "l"(src));
}
__device__ __forceinline__ void ldm4(uint32_t* r, uint32_t addr) {
    asm volatile("ldmatrix.sync.aligned.m8n8.x4.shared.b16 {%0,%1,%2,%3}, [%4];"
                 : "=r"(r[0]), "=r"(r[1]), "=r"(r[2]), "=r"(r[3]) : "r"(addr));
}
__device__ __forceinline__ void ldm4t(uint32_t* r, uint32_t addr) {
    asm volatile("ldmatrix.sync.aligned.m8n8.x4.trans.shared.b16 {%0,%1,%2,%3}, [%4];"
                 : "=r"(r[0]), "=r"(r[1]), "=r"(r[2]), "=r"(r[3]) : "r"(addr));
}
__device__ __forceinline__ void mma_f16(float c[4], const uint32_t a[4],
                                        uint32_t b0, uint32_t b1) {
    asm volatile(
        "mma.sync.aligned.m16n8k16.row.col.f32.f16.f16.f32 "
        "{%0,%1,%2,%3}, {%4,%5,%6,%7}, {%8,%9}, {%0,%1,%2,%3};"
        : "+f"(c[0]), "+f"(c[1]), "+f"(c[2]), "+f"(c[3])
        : "r"(a[0]), "r"(a[1]), "r"(a[2]), "r"(a[3]), "r"(b0), "r"(b1));
}
__device__ __forceinline__ uint32_t pack2(h16 a, h16 b) {
    return (uint32_t)__half_as_ushort(a) | ((uint32_t)__half_as_ushort(b) << 16);
}
__device__ __forceinline__ void gdc_wait() {
    asm volatile("griddepcontrol.wait;" ::: "memory");
}
__device__ __forceinline__ void gdc_launch() {
    asm volatile("griddepcontrol.launch_dependents;" ::: "memory");
}

// ---------------- GEMM geometry: CTA 128x128, warp 64x32, BK=64, 3 stages ----
#define RST 144                       // A row: 128B data + 16B pad
#define RSTB 272                      // trans-B row: 256B data + 16B pad
#define A_B (128 * RST)               // 18432
#define OB_OFF A_B
#define STG_NT (2 * A_B)              // 36864
#define STG_TR (A_B + 64 * RSTB)      // 35840
#define NST 3
#define SMEM_G (NST * STG_NT)         // 110592 -> 2 CTAs/SM

// C[z+ZOFF] = alpha * A[z+ZOFF] @ op(B[z+ZOFF]);  A: [M,K] rows fp16.
// BTRANS=0: B is [N,K] rows. BTRANS=1: B is [K,N] rows (trans-ldmatrix).
// EPI 0: fp32 to Cf.  EPI 1: fp16 to Ch.
// MODE 0: dense.
// MODE 3: triangular-packed causal grid (heavy m first), blockIdx.z = batch.
// MODE 4: flattened PV grid: y encodes (m-tile, batch), heavy m first,
//         K truncated at m0+128.
template<int EPI, int MODE, int BTRANS, int ZOFF>
__global__ void __launch_bounds__(256, 2)
gemm_f16(const h16* __restrict__ A, const h16* __restrict__ B,
         float* __restrict__ Cf, h16* __restrict__ Ch,
         int M, int N, int K, size_t sA, size_t sB, size_t sC, float alpha)
{
    constexpr int STG_B = BTRANS ? STG_TR : STG_NT;
    int m0, n0, z;
    int KT = K / 64;
    if (MODE == 3) {
        const int t = (int)(gridDim.x - 1 - blockIdx.x);   // heavy (large m) first
        int mt = (int)((sqrtf(8.0f * (float)t + 1.0f) - 1.0f) * 0.5f);
        while ((mt + 1) * (mt + 2) / 2 <= t) mt++;
        while (mt * (mt + 1) / 2 > t) mt--;
        const int nt = t - mt * (mt + 1) / 2;
        m0 = mt * 128;
        n0 = nt * 128;
        z  = blockIdx.z + ZOFF;
    } else if (MODE == 4) {
        const int yy = (int)(gridDim.y - 1 - blockIdx.y);  // heavy first, batch-interleaved
        const int mt = yy >> 2;
        z  = (yy & 3) + ZOFF;
        m0 = mt * 128;
        n0 = blockIdx.x * 128;
        int kmax = m0 + 128;
        if (kmax < K) KT = kmax / 64;
    } else {
        m0 = blockIdx.y * 128;
        n0 = blockIdx.x * 128;
        z  = blockIdx.z + ZOFF;
    }

    extern __shared__ char smem[];
    const uint32_t sbase = smem_u32(smem);
    const int tid  = threadIdx.x;
    const int lane = tid & 31;
    const int wid  = tid >> 5;
    const int wm   = (wid >> 2) * 64;
    const int wn   = (wid & 3) * 32;

    const h16* pA = A + (size_t)z * sA;
    const h16* pB = B + (size_t)z * sB;

    auto load_stage = [&](int s, int kt) {
        if (kt < KT) {
            const uint32_t st = sbase + (uint32_t)s * STG_B;
            const size_t k0 = (size_t)kt * 64;
#pragma unroll
            for (int i = 0; i < 4; i++) {          // A: 128 rows x 8 segs
                const int slot = tid + i * 256;
                const int row = slot >> 3;
                const int seg = slot & 7;
                cp16(st + (uint32_t)(row * RST + seg * 16),
                     pA + (size_t)(m0 + row) * K + k0 + seg * 8);
            }
            if (BTRANS) {
#pragma unroll
                for (int i = 0; i < 4; i++) {      // B: 64 k-rows x 16 segs
                    const int slot = tid + i * 256;
                    const int row = slot >> 4;
                    const int seg = slot & 15;
                    cp16(st + OB_OFF + (uint32_t)(row * RSTB + seg * 16),
                         pB + (k0 + row) * (size_t)N + n0 + seg * 8);
                }
            } else {
#pragma unroll
                for (int i = 0; i < 4; i++) {      // B: 128 n-rows x 8 segs
                    const int slot = tid + i * 256;
                    const int row = slot >> 3;
                    const int seg = slot & 7;
                    cp16(st + OB_OFF + (uint32_t)(row * RST + seg * 16),
                         pB + (size_t)(n0 + row) * K + k0 + seg * 8);
                }
            }
        }
        asm volatile("cp.async.commit_group;" ::: "memory");
    };

    // ldmatrix lane addressing
    const int arow = lane & 15;
    const int akh  = lane >> 4;
    const uint32_t aoff = (uint32_t)((wm + arow) * RST + akh * 16);
    const int nrow = (lane & 7) + ((lane >> 4) << 3);
    const int bkh  = (lane >> 3) & 1;
    const uint32_t boffN = (uint32_t)((wn + nrow) * RST + bkh * 16);
    const int btrow = (lane & 7) + (((lane >> 3) & 1) << 3);
    const uint32_t boffT = (uint32_t)(btrow * RSTB + (((lane >> 4) << 3) + wn) * 2);

    float acc[4][4][4];
#pragma unroll
    for (int i = 0; i < 4; i++)
#pragma unroll
        for (int j = 0; j < 4; j++)
#pragma unroll
            for (int q = 0; q < 4; q++) acc[i][j][q] = 0.0f;

    gdc_wait();
    load_stage(0, 0);
    load_stage(1, 1);

    for (int it = 0; it < KT; it++) {
        const int s = it % NST;
        asm volatile("cp.async.wait_group 1;" ::: "memory");
        __syncthreads();
        load_stage((it + 2) % NST, it + 2);   // stage (it-1)%NST: readers done last iter
        const uint32_t stg = sbase + (uint32_t)s * STG_B;
#pragma unroll
        for (int ks = 0; ks < 4; ks++) {
            uint32_t a[4][4], b[4][2];
#pragma unroll
            for (int mt = 0; mt < 4; mt++)
                ldm4(a[mt], stg + aoff + mt * (16 * RST) + ks * 32);
#pragma unroll
            for (int ntp = 0; ntp < 2; ntp++) {
                uint32_t t[4];
                if (BTRANS)
                    ldm4t(t, stg + OB_OFF + boffT + ks * (16 * RSTB) + ntp * 32);
                else
                    ldm4(t, stg + OB_OFF + boffN + ntp * (16 * RST) + ks * 32);
                b[2*ntp][0] = t[0]; b[2*ntp][1] = t[1];
                b[2*ntp+1][0] = t[2]; b[2*ntp+1][1] = t[3];
            }
#pragma unroll
            for (int mt = 0; mt < 4; mt++)
#pragma unroll
                for (int nt = 0; nt < 4; nt++)
                    mma_f16(acc[mt][nt], a[mt], b[nt][0], b[nt][1]);
        }
    }

    gdc_launch();

    // ---- epilogue ----
    const int r0 = wm + (lane >> 2);
    const int c0 = wn + (lane & 3) * 2;
#pragma unroll
    for (int mt = 0; mt < 4; mt++) {
#pragma unroll
        for (int nt = 0; nt < 4; nt++) {
            const int row = m0 + r0 + mt * 16;
            const int col = n0 + c0 + nt * 8;
            const float v0 = acc[mt][nt][0] * alpha, v1 = acc[mt][nt][1] * alpha;
            const float v2 = acc[mt][nt][2] * alpha, v3 = acc[mt][nt][3] * alpha;
            const size_t o0 = (size_t)z * sC + (size_t)row * N + col;
            const size_t o1 = (size_t)z * sC + (size_t)(row + 8) * N + col;
            if (EPI == 0) {
                Cf[o0] = v0; Cf[o0 + 1] = v1;
                Cf[o1] = v2; Cf[o1 + 1] = v3;
            } else {
                *reinterpret_cast<uint32_t*>(Ch + o0) =
                    pack2(__float2half_rn(v0), __float2half_rn(v1));
                *reinterpret_cast<uint32_t*>(Ch + o1) =
                    pack2(__float2half_rn(v2), __float2half_rn(v3));
            }
        }
    }
}

// ---------------- conversions (split for stream overlap) ----------------
__global__ __launch_bounds__(256) void convert_x_kernel(
    const float* __restrict__ x, h16* __restrict__ x16)
{
    const size_t n4 = (size_t)XR * DD / 4;
    for (size_t i = (size_t)blockIdx.x * 256 + threadIdx.x; i < n4; i += (size_t)gridDim.x * 256) {
        const float4 v = reinterpret_cast<const float4*>(x)[i];
        uint2 o;
        o.x = pack2(__float2half_rn(v.x), __float2half_rn(v.y));
        o.y = pack2(__float2half_rn(v.z), __float2half_rn(v.w));
        reinterpret_cast<uint2*>(x16)[i] = o;
    }
    gdc_launch();
}

__global__ __launch_bounds__(256) void convert_w_kernel(
    const float* __restrict__ W0, const float* __restrict__ W1,
    const float* __restrict__ W2, h16* __restrict__ w16)
{
    const int zz = blockIdx.z;
    const float* in = (zz == 0) ? W0 : (zz == 1) ? W1 : W2;
    h16* out = w16 + (size_t)zz * DD * DD;
    const size_t n4 = (size_t)DD * DD / 4;
    for (size_t i = (size_t)blockIdx.x * 256 + threadIdx.x; i < n4; i += (size_t)gridDim.x * 256) {
        const float4 v = reinterpret_cast<const float4*>(in)[i];
        uint2 o;
        o.x = pack2(__float2half_rn(v.x), __float2half_rn(v.y));
        o.y = pack2(__float2half_rn(v.z), __float2half_rn(v.w));
        reinterpret_cast<uint2*>(out)[i] = o;
    }
    gdc_launch();
}

// trivial root kernel: origin of the capture fork (cheap, one block)
__global__ void root_kernel() {}

// causal softmax over fp16 scores (scaled in GEMM); one block of 256 per row.
__global__ __launch_bounds__(256) void softmax_kernel(
    const h16* __restrict__ S, h16* __restrict__ Ph)
{
    const int row = blockIdx.x & (SS - 1);
    const int b   = blockIdx.x >> 11;
    const size_t base = ((size_t)b * SS + row) * SS;
    const int L = row + 1;
    const int tid  = threadIdx.x;
    const int lane = tid & 31;
    const int wrp  = tid >> 5;

    gdc_wait();
    const uint4 sv = reinterpret_cast<const uint4*>(S + base)[tid];
    const int e0 = tid * 8;
    float v[8];
    {
        float2 f;
        f = __half22float2(*reinterpret_cast<const __half2*>(&sv.x)); v[0] = f.x; v[1] = f.y;
        f = __half22float2(*reinterpret_cast<const __half2*>(&sv.y)); v[2] = f.x; v[3] = f.y;
        f = __half22float2(*reinterpret_cast<const __half2*>(&sv.z)); v[4] = f.x; v[5] = f.y;
        f = __half22float2(*reinterpret_cast<const __half2*>(&sv.w)); v[6] = f.x; v[7] = f.y;
    }

    float m = -INFINITY;
#pragma unroll
    for (int q = 0; q < 8; q++) if (e0 + q < L) m = fmaxf(m, v[q]);

    __shared__ float red[8];
#pragma unroll
    for (int o = 16; o > 0; o >>= 1) m = fmaxf(m, __shfl_xor_sync(0xFFFFFFFFu, m, o));
    if (lane == 0) red[wrp] = m;
    __syncthreads();
#pragma unroll
    for (int w = 0; w < 8; w++) m = fmaxf(m, red[w]);
    __syncthreads();

    float sum = 0.0f;
#pragma unroll
    for (int q = 0; q < 8; q++) {
        v[q] = (e0 + q < L) ? __expf(v[q] - m) : 0.0f;
        sum += v[q];
    }
#pragma unroll
    for (int o = 16; o > 0; o >>= 1) sum += __shfl_xor_sync(0xFFFFFFFFu, sum, o);
    if (lane == 0) red[wrp] = sum;
    __syncthreads();
    sum = 0.0f;
#pragma unroll
    for (int w = 0; w < 8; w++) sum += red[w];
    const float inv = 1.0f / sum;
    gdc_launch();

    uint4 ov;
    ov.x = pack2(__float2half_rn(v[0] * inv), __float2half_rn(v[1] * inv));
    ov.y = pack2(__float2half_rn(v[2] * inv), __float2half_rn(v[3] * inv));
    ov.z = pack2(__float2half_rn(v[4] * inv), __float2half_rn(v[5] * inv));
    ov.w = pack2(__float2half_rn(v[6] * inv), __float2half_rn(v[7] * inv));
    reinterpret_cast<uint4*>(Ph + base)[tid] = ov;
}

// ---------------- PDL launch helper ----------------
static void launch_pdl(const void* func, dim3 grid, dim3 block, size_t smem,
                       void** args, cudaStream_t st)
{
    cudaLaunchConfig_t cfg = {};
    cfg.gridDim = grid;
    cfg.blockDim = block;
    cfg.dynamicSmemBytes = smem;
    cfg.stream = st;
    cudaLaunchAttribute attr[1];
    attr[0].id = cudaLaunchAttributeProgrammaticStreamSerialization;
    attr[0].val.programmaticStreamSerializationAllowed = 1;
    cfg.attrs = attr;
    cfg.numAttrs = 1;
    if (cudaLaunchKernelExC(&cfg, func, args) != cudaSuccess) {
        cudaLaunchKernel(func, grid, block, args, smem, st);
    }
}

// ---------------- launch ----------------
extern "C" void kernel_launch(void* const* d_in, const int* in_sizes, int n_in,
                              void* d_out, int out_size)
{
    const float* x  = (const float*)d_in[0];
    const float* Wq = (const float*)d_in[1];
    const float* Wk = (const float*)d_in[2];
    const float* Wv = (const float*)d_in[3];
    float* out = (float*)d_out;

    h16 *x16, *w16, *QKV, *Ph;
    float* P;
    cudaGetSymbolAddress((void**)&x16, g_x16);
    cudaGetSymbolAddress((void**)&w16, g_w16);
    cudaGetSymbolAddress((void**)&QKV, g_QKV);
    cudaGetSymbolAddress((void**)&P,   g_P);
    cudaGetSymbolAddress((void**)&Ph,  g_Ph);
    h16* Sh = (h16*)P;   // fp16 score buffer aliasing g_P

    cudaFuncSetAttribute(gemm_f16<1,0,1,0>, cudaFuncAttributeMaxDynamicSharedMemorySize, SMEM_G);
    cudaFuncSetAttribute(gemm_f16<1,0,1,2>, cudaFuncAttributeMaxDynamicSharedMemorySize, SMEM_G);
    cudaFuncSetAttribute(gemm_f16<1,3,0,0>, cudaFuncAttributeMaxDynamicSharedMemorySize, SMEM_G);
    cudaFuncSetAttribute(gemm_f16<0,4,1,0>, cudaFuncAttributeMaxDynamicSharedMemorySize, SMEM_G);

    // one-time side stream + events (reused every call; no device-mem allocs)
    static cudaStream_t s2 = nullptr;
    static cudaEvent_t evRoot = nullptr, evX = nullptr, evW = nullptr, evJoin = nullptr;
    if (s2 == nullptr) {
        cudaStreamCreateWithFlags(&s2, cudaStreamNonBlocking);
        cudaEventCreateWithFlags(&evRoot, cudaEventDisableTiming);
        cudaEventCreateWithFlags(&evX, cudaEventDisableTiming);
        cudaEventCreateWithFlags(&evW, cudaEventDisableTiming);
        cudaEventCreateWithFlags(&evJoin, cudaEventDisableTiming);
    }

    size_t WSZ = (size_t)DD * DD;
    size_t QSZ = (size_t)XR * DD;
    const float scale = 1.0f / sqrtf((float)DD);
    h16* nullh = nullptr;
    float* nullf = nullptr;

    // 0. capture-legal fork: root kernel on stream 0, s2 joins via event wait
    root_kernel<<<1, 32, 0, 0>>>();
    cudaEventRecord(evRoot, 0);
    cudaStreamWaitEvent(s2, evRoot, 0);

    // 1. conversions in parallel: x on stream 0, W on side stream
    convert_x_kernel<<<2048, 256, 0, 0>>>(x, x16);
    convert_w_kernel<<<dim3(512, 1, 3), 256, 0, s2>>>(Wq, Wk, Wv, w16);

    // cross-join: each stream needs both conversions done
    cudaEventRecord(evX, 0);
    cudaEventRecord(evW, s2);
    cudaStreamWaitEvent(0, evW, 0);
    cudaStreamWaitEvent(s2, evX, 0);

    // 2a. V projection (z=2) on side stream — needed only by PV
    {
        int M = XR, N = DD, K = DD;
        size_t sA = 0, sB = WSZ, sC = QSZ;
        float alpha = 1.0f;
        void* args[] = {&x16, &w16, &nullf, &QKV, &M, &N, &K, &sA, &sB, &sC, &alpha};
        launch_pdl((const void*)gemm_f16<1,0,1,2>, dim3(DD/128, XR/128, 1), 256, SMEM_G, args, s2);
    }

    // 2b. Q,K projections (z=0,1) on stream 0
    {
        int M = XR, N = DD, K = DD;
        size_t sA = 0, sB = WSZ, sC = QSZ;
        float alpha = 1.0f;
        void* args[] = {&x16, &w16, &nullf, &QKV, &M, &N, &K, &sA, &sB, &sC, &alpha};
        launch_pdl((const void*)gemm_f16<1,0,1,0>, dim3(DD/128, XR/128, 2), 256, SMEM_G, args, 0);
    }

    // 3. scores (fp16 out, scaled): S[b] = scale * Q[b] @ K[b]^T
    //    triangular-packed grid: 136 live tiles per batch, heavy-m first
    {
        int M = SS, N = SS, K = DD;
        size_t sA = (size_t)SS*DD, sB = (size_t)SS*DD, sC = (size_t)SS*SS;
        float alpha = scale;
        const h16* Qp = QKV;
        const h16* Kp = QKV + QSZ;
        void* args[] = {&Qp, &Kp, &nullf, &Sh, &M, &N, &K, &sA, &sB, &sC, &alpha};
        launch_pdl((const void*)gemm_f16<1,3,0,0>, dim3(136, 1, BB), 256, SMEM_G, args, 0);
    }

    // 4. causal softmax (fp16 in) -> fp16 P on stream 0
    {
        const h16* Sp = Sh;
        void* args[] = {&Sp, &Ph};
        launch_pdl((const void*)softmax_kernel, dim3(BB * SS), 256, 0, args, 0);
    }

    // join: stream 0 waits for V projection
    cudaEventRecord(evJoin, s2);
    cudaStreamWaitEvent(0, evJoin, 0);

    // 5. out[b] = P[b] @ V[b] (K truncated at diagonal), flattened heavy-first
    //    grid y encodes (m-tile, batch) so all batches' heavy tiles pack first
    {
        int M = SS, N = DD, K = SS;
        size_t sA = (size_t)SS*SS, sB = (size_t)SS*DD, sC = (size_t)SS*DD;
        float alpha = 1.0f;
        const h16* Pp = Ph;
        const h16* Vp = QKV + 2*QSZ;
        void* args[] = {&Pp, &Vp, &out, &nullh, &M, &N, &K, &sA, &sB, &sC, &alpha};
        launch_pdl((const void*)gemm_f16<0,4,1,0>, dim3(DD/128, (SS/128) * BB, 1), 256, SMEM_G, args, 0);
    }
}